// round 11
// baseline (speedup 1.0000x reference)
#include <cuda_runtime.h>
#include <cuda_fp16.h>
#include <cstdint>

#define B_SIZE 4096
#define T_LEN  2048
#define H_DIM  32
#define THREADS 128
#define WARPS  (THREADS/32)
#define GRID   592

__device__ int g_task_counter;
__device__ int g_order[B_SIZE];

// ---- fast transcendentals: single-MUFU tanh (sm_75+) ----
__device__ __forceinline__ float tanha(float x) {
    float r; asm("tanh.approx.f32 %0, %1;" : "=f"(r) : "f"(x)); return r;
}
__device__ __forceinline__ float ex2f(float x) {
    float r; asm("ex2.approx.f32 %0, %1;" : "=f"(r) : "f"(x)); return r;
}
#define L2E 1.4426950408889634f

// sigmoid(z) = 0.5*tanh(z/2) + 0.5   (1 MUFU)
__device__ __forceinline__ float sigf(float z) {
    return fmaf(0.5f, tanha(0.5f * z), 0.5f);
}

// ---- LPT scheduler: order tasks longest-first (16-step buckets) ----
__global__ void __launch_bounds__(128)
schedule_kernel(const int* __restrict__ lengths)
{
    __shared__ int s_hist[128];
    __shared__ int s_base[128];
    const int tid = threadIdx.x;
    s_hist[tid] = 0;
    __syncthreads();
    for (int i = tid; i < B_SIZE; i += 128) {
        int b = (T_LEN - lengths[i]) >> 4;   // bucket 0 = longest
        atomicAdd(&s_hist[b], 1);
    }
    __syncthreads();
    if (tid == 0) {
        int acc = 0;
        for (int b = 0; b < 128; b++) { s_base[b] = acc; acc += s_hist[b]; }
        g_task_counter = 0;
    }
    __syncthreads();
    s_hist[tid] = 0;
    __syncthreads();
    for (int i = tid; i < B_SIZE; i += 128) {
        int b = (T_LEN - lengths[i]) >> 4;
        int pos = s_base[b] + atomicAdd(&s_hist[b], 1);
        g_order[pos] = i;
    }
}

__global__ void __launch_bounds__(THREADS, 4)
bilstm_kernel(const float* __restrict__ x,
              const int*   __restrict__ lengths,
              const float* __restrict__ w_ih,
              const float* __restrict__ w_hh,
              const float* __restrict__ b_ih,
              const float* __restrict__ b_hh,
              const float* __restrict__ fc_w,
              const float* __restrict__ fc_b,
              const float* __restrict__ fc2_w,
              const float* __restrict__ fc2_b,
              float* __restrict__ out)
{
    // per-warp double-buffered h in f16: 2 bufs x 32 halves = 128 B per warp
    __shared__ __align__(16) __half s_h[WARPS * 64];

    const int tid  = threadIdx.x;
    const int lane = tid & 31;
    const int wid  = tid >> 5;

    // ---- per-lane recurrent weights as f16x2 (64 regs total) ----
    const int l = lane;
    const float bci = b_ih[l]      + b_hh[l];
    const float bcf = b_ih[32 + l] + b_hh[32 + l];
    const float bcg = b_ih[64 + l] + b_hh[64 + l];
    const float bco = b_ih[96 + l] + b_hh[96 + l];
    const float wxi = w_ih[l], wxf = w_ih[32 + l], wxg = w_ih[64 + l], wxo = w_ih[96 + l];

    __half2 wI[16], wF[16], wG[16], wO[16];
    {
        const float* pI = w_hh + (0  + l) * H_DIM;
        const float* pF = w_hh + (32 + l) * H_DIM;
        const float* pG = w_hh + (64 + l) * H_DIM;
        const float* pO = w_hh + (96 + l) * H_DIM;
        #pragma unroll
        for (int j = 0; j < 16; j++) {
            wI[j] = __floats2half2_rn(pI[2*j], pI[2*j + 1]);
            wF[j] = __floats2half2_rn(pF[2*j], pF[2*j + 1]);
            wG[j] = __floats2half2_rn(pG[2*j], pG[2*j + 1]);
            wO[j] = __floats2half2_rn(pO[2*j], pO[2*j + 1]);
        }
    }

    __half* hb = s_h + wid * 64;

    for (;;) {
        unsigned tk = 0;
        if (lane == 0) tk = (unsigned)atomicAdd(&g_task_counter, 1);
        tk = __shfl_sync(0xffffffffu, tk, 0);
        if (tk >= B_SIZE) break;
        const int task = g_order[tk];

        const int len = lengths[task];
        const float* xb = x + (size_t)task * T_LEN;

        float c = 0.f;
        int pb = 0;
        hb[lane] = __float2half_rn(0.f);
        __syncwarp();

        int t = len - 1;
        float xv = __ldg(xb + t);
        while (t >= 0) {
            const int tn = (t > 0) ? (t - 1) : 0;
            const float xn = __ldg(xb + tn);   // prefetch next x

            // f32 init term (exact): bias + x * w_ih
            const float pi = fmaf(xv, wxi, bci);
            const float pf = fmaf(xv, wxf, bcf);
            const float pg = fmaf(xv, wxg, bcg);
            const float po = fmaf(xv, wxo, bco);

            // load h (16 half2 = 64 B) via 4 LDS.128
            uint32_t hq[16];
            {
                const uint4* hp = (const uint4*)(hb + pb);
                *(uint4*)(hq + 0)  = hp[0];
                *(uint4*)(hq + 4)  = hp[1];
                *(uint4*)(hq + 8)  = hp[2];
                *(uint4*)(hq + 12) = hp[3];
            }

            // matvec: 64 HFMA2, 8 independent chains (2 per gate, 8 deep)
            __half2 z = __float2half2_rn(0.f);
            __half2 aI0 = z, aI1 = z, aF0 = z, aF1 = z;
            __half2 aG0 = z, aG1 = z, aO0 = z, aO1 = z;
            #pragma unroll
            for (int j = 0; j < 8; j++) {
                const __half2 q0 = *reinterpret_cast<const __half2*>(&hq[2*j]);
                const __half2 q1 = *reinterpret_cast<const __half2*>(&hq[2*j + 1]);
                aI0 = __hfma2(wI[2*j],     q0, aI0);
                aF0 = __hfma2(wF[2*j],     q0, aF0);
                aG0 = __hfma2(wG[2*j],     q0, aG0);
                aO0 = __hfma2(wO[2*j],     q0, aO0);
                aI1 = __hfma2(wI[2*j + 1], q1, aI1);
                aF1 = __hfma2(wF[2*j + 1], q1, aF1);
                aG1 = __hfma2(wG[2*j + 1], q1, aG1);
                aO1 = __hfma2(wO[2*j + 1], q1, aO1);
            }

            // reduce: half2 add, convert to f32, fold into exact init term
            float2 r;
            r = __half22float2(__hadd2(aI0, aI1)); const float gi = pi + r.x + r.y;
            r = __half22float2(__hadd2(aF0, aF1)); const float gf = pf + r.x + r.y;
            r = __half22float2(__hadd2(aG0, aG1)); const float gg = pg + r.x + r.y;
            r = __half22float2(__hadd2(aO0, aO1)); const float go = po + r.x + r.y;

            const float iv = sigf(gi);
            const float fv = sigf(gf);
            const float gv = tanha(gg);
            const float ov = sigf(go);
            c = fmaf(fv, c, iv * gv);
            const float hn = ov * tanha(c);

            pb ^= 32;
            hb[pb + lane] = __float2half_rn(hn);
            __syncwarp();
            xv = xn;
            --t;
        }

        // ---- FC head (cold path) ----
        {
            float u0 = __ldg(fc_b + lane);
            float u1 = __ldg(fc_b + 32 + lane);
            #pragma unroll
            for (int k = 0; k < 32; k++) {
                const float hk = __half2float(hb[pb + k]);   // broadcast read
                u0 = fmaf(__ldg(fc_w + lane * 32 + k),        hk, u0);
                u1 = fmaf(__ldg(fc_w + (32 + lane) * 32 + k), hk, u1);
            }
            u0 = (u0 > 0.f) ? u0 : (ex2f(L2E * u0) - 1.f);
            u1 = (u1 > 0.f) ? u1 : (ex2f(L2E * u1) - 1.f);

            float part = u0 * __ldg(fc2_w + lane) + u1 * __ldg(fc2_w + 32 + lane);
            #pragma unroll
            for (int s = 16; s; s >>= 1) part += __shfl_xor_sync(0xffffffffu, part, s);
            if (lane == 0) out[task] = sigf(part + __ldg(fc2_b));
            __syncwarp();   // protect hb reuse across tasks
        }
    }
}

extern "C" void kernel_launch(void* const* d_in, const int* in_sizes, int n_in,
                              void* d_out, int out_size)
{
    const float* x       = (const float*)d_in[0];
    const int*   lengths = (const int*)  d_in[1];
    const float* w_ih    = (const float*)d_in[2];
    const float* w_hh    = (const float*)d_in[3];
    const float* b_ih    = (const float*)d_in[4];
    const float* b_hh    = (const float*)d_in[5];
    const float* fc_w    = (const float*)d_in[6];
    const float* fc_b    = (const float*)d_in[7];
    const float* fc2_w   = (const float*)d_in[8];
    const float* fc2_b   = (const float*)d_in[9];
    float* out = (float*)d_out;

    schedule_kernel<<<1, 128>>>(lengths);
    bilstm_kernel<<<GRID, THREADS>>>(x, lengths, w_ih, w_hh, b_ih, b_hh,
                                     fc_w, fc_b, fc2_w, fc2_b, out);
}